// round 13
// baseline (speedup 1.0000x reference)
#include <cuda_runtime.h>
#include <cuda_fp16.h>
#include <cstdint>

// Shape fixed by reference:
//   query [B=16, Lq=2048, D=512] f32, value [B=16, Lv=2048, D=512] f32
//   out = context [B,Lq,D] f32  ||  attn [B,Lq,Lv] f32
static constexpr int B_ = 16, LQ = 2048, LV = 2048, DD = 512;
static constexpr int NCH = 4, CB = B_ / NCH;  // 4 chunks of 4 batches

static constexpr size_t NQ = (size_t)B_ * LQ * DD;
static constexpr size_t NV = (size_t)B_ * LV * DD;
static constexpr size_t NP = (size_t)B_ * LQ * LV;

// fp16 hi/lo scratch (global)
__device__ __half g_Qhi[NQ], g_Qlo[NQ];
__device__ __half g_Vhi[NV], g_Vlo[NV];
__device__ __half g_VThi[NV];                 // [b][d][v]
__device__ __half g_Phi[NP];

// ---------------------------------------------------------------------------
// helpers
// ---------------------------------------------------------------------------
__device__ __forceinline__ void cp16(uint32_t dst, const void* src) {
    asm volatile("cp.async.cg.shared.global [%0], [%1], 16;" :: "r"(dst), "l"(src));
}
#define CP_COMMIT() asm volatile("cp.async.commit_group;" ::: "memory")
template <int N>
__device__ __forceinline__ void cp_wait() {
    asm volatile("cp.async.wait_group %0;" :: "n"(N) : "memory");
}

// split pair (x,y) -> hi half2 (low = x), lo half2
__device__ __forceinline__ void f16_split2(float x, float y,
                                           uint32_t& hp, uint32_t& lp) {
    __half2 h = __floats2half2_rn(x, y);
    hp = *reinterpret_cast<uint32_t*>(&h);
    float2 hf = __half22float2(h);
    __half2 l = __floats2half2_rn(x - hf.x, y - hf.y);
    lp = *reinterpret_cast<uint32_t*>(&l);
}

__device__ __forceinline__ void mma16(float* d, const uint32_t* a, const uint32_t* b) {
    asm volatile(
        "mma.sync.aligned.m16n8k16.row.col.f32.f16.f16.f32 "
        "{%0,%1,%2,%3}, {%4,%5,%6,%7}, {%8,%9}, {%0,%1,%2,%3};"
        : "+f"(d[0]), "+f"(d[1]), "+f"(d[2]), "+f"(d[3])
        : "r"(a[0]), "r"(a[1]), "r"(a[2]), "r"(a[3]), "r"(b[0]), "r"(b[1]));
}

__device__ __forceinline__ void ldm4(uint32_t* r, uint32_t addr) {
    asm volatile("ldmatrix.sync.aligned.m8n8.x4.shared.b16 {%0,%1,%2,%3}, [%4];"
                 : "=r"(r[0]), "=r"(r[1]), "=r"(r[2]), "=r"(r[3]) : "r"(addr));
}

// ---------------------------------------------------------------------------
// fp16 split GEMM:  C[M,N] = A[M,K]*B[N,K]^T, batched via blockIdx.z
// PASSES=3: Ahi*Bhi + Ahi*Blo + Alo*Bhi  (full compensation, 4 tiles/stage)
// PASSES=1: Ahi*Bhi                       (2 tiles/stage, deeper pipeline)
// CTA 128x128, BK=32, 8 warps (2x4 of 64x32), STAGES-deep cp.async,
// XOR-swizzled smem (64B rows, chunk c ^= (r>>1)&3), ldmatrix feeds.
// ---------------------------------------------------------------------------
static constexpr int ROWB   = 64;              // bytes per smem row (32 halves)
static constexpr int TILE_B = 128 * ROWB;      // 8 KB
template <int PASSES> struct StageTiles { static constexpr int v = 4; };
template <> struct StageTiles<1> { static constexpr int v = 2; };
static constexpr int GEMM_SMEM = 96 * 1024;    // both configs use 96 KB

template <int PASSES, int STAGES>
__global__ __launch_bounds__(256, 2)
void mma_f16_gemm(const __half* __restrict__ Ahi,
                  const __half* __restrict__ Alo,
                  const __half* __restrict__ Bhi,
                  const __half* __restrict__ Blo,
                  float* __restrict__ C, int M, int N, int K)
{
    constexpr int STAGE_B = StageTiles<PASSES>::v * TILE_B;
    constexpr int PREF    = STAGES - 1;
    constexpr int BOFF    = (PASSES == 3 ? 2 : 1) * TILE_B;

    extern __shared__ char smc[];
    const uint32_t base = (uint32_t)__cvta_generic_to_shared(smc);

    const int tid = threadIdx.x;
    const int wid = tid >> 5, lane = tid & 31;
    const int gid = lane >> 2, tig = lane & 3;
    const int wm  = wid & 1;
    const int wn  = wid >> 1;

    const size_t bz = blockIdx.z;
    Ahi += bz * (size_t)M * K;  Alo += bz * (size_t)M * K;
    Bhi += bz * (size_t)N * K;  Blo += bz * (size_t)N * K;
    C   += bz * (size_t)M * N;
    const int row0 = blockIdx.y * 128;
    const int col0 = blockIdx.x * 128;

    // loader: chunks of 16B; thread does chunks tid, tid+256
    const int i0 = tid, i1 = tid + 256;
    const int r0 = i0 >> 2, c0 = i0 & 3;
    const int r1 = i1 >> 2, c1 = i1 & 3;
    const uint32_t s0 = (uint32_t)(r0 * ROWB + ((c0 ^ ((r0 >> 1) & 3)) << 4));
    const uint32_t s1 = (uint32_t)(r1 * ROWB + ((c1 ^ ((r1 >> 1) & 3)) << 4));

    auto load_stage = [&](int st, int k0) {
        const uint32_t sb = base + (uint32_t)(st * STAGE_B);
        cp16(sb + s0,            &Ahi[(size_t)(row0 + r0) * K + k0 + c0 * 8]);
        cp16(sb + s1,            &Ahi[(size_t)(row0 + r1) * K + k0 + c1 * 8]);
        if (PASSES == 3) {
            cp16(sb + TILE_B + s0, &Alo[(size_t)(row0 + r0) * K + k0 + c0 * 8]);
            cp16(sb + TILE_B + s1, &Alo[(size_t)(row0 + r1) * K + k0 + c1 * 8]);
        }
        cp16(sb + BOFF + s0,     &Bhi[(size_t)(col0 + r0) * K + k0 + c0 * 8]);
        cp16(sb + BOFF + s1,     &Bhi[(size_t)(col0 + r1) * K + k0 + c1 * 8]);
        if (PASSES == 3) {
            cp16(sb + BOFF + TILE_B + s0, &Blo[(size_t)(col0 + r0) * K + k0 + c0 * 8]);
            cp16(sb + BOFF + TILE_B + s1, &Blo[(size_t)(col0 + r1) * K + k0 + c1 * 8]);
        }
    };

    // ldmatrix lane addressing
    const int a_row16 = ((lane >> 3) & 1) * 8 + (lane & 7);
    const int a_cpar  = (lane >> 4) & 1;
    uint32_t aoff[4]; int aswz[4];
#pragma unroll
    for (int mt = 0; mt < 4; ++mt) {
        const int r = wm * 64 + mt * 16 + a_row16;
        aoff[mt] = (uint32_t)(r * ROWB);
        aswz[mt] = (r >> 1) & 3;
    }
    const int b_nadd = ((lane >> 4) & 1) * 8 + (lane & 7);
    const int b_cpar = (lane >> 3) & 1;
    uint32_t boff[2]; int bswz[2];
#pragma unroll
    for (int p = 0; p < 2; ++p) {
        const int n = wn * 32 + p * 16 + b_nadd;
        boff[p] = (uint32_t)(n * ROWB);
        bswz[p] = (n >> 1) & 3;
    }

    float acc[4][4][4];
#pragma unroll
    for (int mt = 0; mt < 4; ++mt)
#pragma unroll
        for (int nt = 0; nt < 4; ++nt)
#pragma unroll
            for (int i = 0; i < 4; ++i) acc[mt][nt][i] = 0.f;

    const int nsl = K / 32;
#pragma unroll
    for (int s = 0; s < PREF; ++s) {
        load_stage(s, s * 32);
        CP_COMMIT();
    }

    for (int s = 0; s < nsl; ++s) {
        cp_wait<PREF - 1>();   // stage s resident
        __syncthreads();       // all warps done with previous use of this buffer

        if (s + PREF < nsl) {
            load_stage((s + PREF) % STAGES, (s + PREF) * 32);
            CP_COMMIT();
        } else {
            CP_COMMIT();       // empty group keeps count aligned for cp_wait
        }

        const uint32_t stg  = base + (uint32_t)((s % STAGES) * STAGE_B);
        const uint32_t Ahib = stg;
        const uint32_t Bhib = stg + BOFF;

#pragma unroll
        for (int ks = 0; ks < 2; ++ks) {
            uint32_t bhi[4][2], blo[4][2];
#pragma unroll
            for (int p = 0; p < 2; ++p) {
                uint32_t t[4];
                const uint32_t ad = Bhib + boff[p] +
                    (uint32_t)(((ks * 2 + b_cpar) ^ bswz[p]) << 4);
                ldm4(t, ad);
                bhi[2 * p][0] = t[0]; bhi[2 * p][1] = t[1];
                bhi[2 * p + 1][0] = t[2]; bhi[2 * p + 1][1] = t[3];
                if (PASSES == 3) {
                    ldm4(t, ad + TILE_B);
                    blo[2 * p][0] = t[0]; blo[2 * p][1] = t[1];
                    blo[2 * p + 1][0] = t[2]; blo[2 * p + 1][1] = t[3];
                }
            }

#pragma unroll
            for (int mt = 0; mt < 4; ++mt) {
                uint32_t ahi[4], alo[4];
                const uint32_t ad = Ahib + aoff[mt] +
                    (uint32_t)(((ks * 2 + a_cpar) ^ aswz[mt]) << 4);
                ldm4(ahi, ad);
                if (PASSES == 3) ldm4(alo, ad + TILE_B);
#pragma unroll
                for (int nt = 0; nt < 4; ++nt) mma16(acc[mt][nt], ahi, bhi[nt]);
                if (PASSES == 3) {
#pragma unroll
                    for (int nt = 0; nt < 4; ++nt) mma16(acc[mt][nt], ahi, blo[nt]);
#pragma unroll
                    for (int nt = 0; nt < 4; ++nt) mma16(acc[mt][nt], alo, bhi[nt]);
                }
            }
        }
    }

    __syncthreads();
#pragma unroll
    for (int mt = 0; mt < 4; ++mt) {
        const int rb = row0 + wm * 64 + mt * 16 + gid;
#pragma unroll
        for (int nt = 0; nt < 4; ++nt) {
            const int cb = col0 + wn * 32 + nt * 8 + 2 * tig;
            *(float2*)&C[(size_t)rb * N + cb] =
                make_float2(acc[mt][nt][0], acc[mt][nt][1]);
            *(float2*)&C[(size_t)(rb + 8) * N + cb] =
                make_float2(acc[mt][nt][2], acc[mt][nt][3]);
        }
    }
}

// ---------------------------------------------------------------------------
// Q split: fp32 -> fp16 hi/lo
// ---------------------------------------------------------------------------
__global__ __launch_bounds__(256)
void split_kernel(const float* __restrict__ X,
                  __half* __restrict__ hi, __half* __restrict__ lo, int n4)
{
    const int i = blockIdx.x * 256 + threadIdx.x;
    if (i >= n4) return;
    float4 v = ((const float4*)X)[i];
    uint32_t h0, l0, h1, l1;
    f16_split2(v.x, v.y, h0, l0);
    f16_split2(v.z, v.w, h1, l1);
    ((uint2*)hi)[i] = make_uint2(h0, h1);
    ((uint2*)lo)[i] = make_uint2(l0, l1);
}

// ---------------------------------------------------------------------------
// Fused V prep (batched via blockIdx.z): Vhi/Vlo [b][v][d] + VThi [b][d][v]
// ---------------------------------------------------------------------------
__global__ __launch_bounds__(256)
void v_prep_kernel(const float* __restrict__ V,
                   __half* __restrict__ Vhi, __half* __restrict__ Vlo,
                   __half* __restrict__ VThi)
{
    __shared__ float t[32][33];
    const int b = blockIdx.z;
    const float* Vb = V + (size_t)b * LV * DD;
    const size_t ro = (size_t)b * LV * DD;
    const size_t to = (size_t)b * DD * LV;
    const int v0 = blockIdx.x * 32, d0 = blockIdx.y * 32;
    const int tx = threadIdx.x, ty = threadIdx.y;  // 32 x 8
#pragma unroll
    for (int i = 0; i < 32; i += 8) {
        float x = Vb[(size_t)(v0 + ty + i) * DD + d0 + tx];
        t[ty + i][tx] = x;
        __half h = __float2half(x);
        Vhi[ro + (size_t)(v0 + ty + i) * DD + d0 + tx] = h;
        Vlo[ro + (size_t)(v0 + ty + i) * DD + d0 + tx] =
            __float2half(x - __half2float(h));
    }
    __syncthreads();
#pragma unroll
    for (int i = 0; i < 32; i += 8)
        VThi[to + (size_t)(d0 + ty + i) * LV + v0 + tx] =
            __float2half(t[tx][ty + i]);
}

// ---------------------------------------------------------------------------
// In-place row softmax over Lv=2048, emits fp16 hi of P
// ---------------------------------------------------------------------------
__global__ __launch_bounds__(256)
void softmax_kernel(float* __restrict__ attn, __half* __restrict__ Phi)
{
    const size_t row = blockIdx.x;
    float4* p = (float4*)(attn + row * (size_t)LV);
    const int tid = threadIdx.x;

    float4 v0 = p[tid * 2 + 0];
    float4 v1 = p[tid * 2 + 1];

    float m = fmaxf(fmaxf(fmaxf(v0.x, v0.y), fmaxf(v0.z, v0.w)),
                    fmaxf(fmaxf(v1.x, v1.y), fmaxf(v1.z, v1.w)));
#pragma unroll
    for (int o = 16; o > 0; o >>= 1)
        m = fmaxf(m, __shfl_xor_sync(0xffffffffu, m, o));

    __shared__ float red[8];
    if ((tid & 31) == 0) red[tid >> 5] = m;
    __syncthreads();
    float mall = red[0];
#pragma unroll
    for (int w = 1; w < 8; ++w) mall = fmaxf(mall, red[w]);
    __syncthreads();

    v0.x = __expf(v0.x - mall); v0.y = __expf(v0.y - mall);
    v0.z = __expf(v0.z - mall); v0.w = __expf(v0.w - mall);
    v1.x = __expf(v1.x - mall); v1.y = __expf(v1.y - mall);
    v1.z = __expf(v1.z - mall); v1.w = __expf(v1.w - mall);

    float s = v0.x + v0.y + v0.z + v0.w + v1.x + v1.y + v1.z + v1.w;
#pragma unroll
    for (int o = 16; o > 0; o >>= 1)
        s += __shfl_xor_sync(0xffffffffu, s, o);
    if ((tid & 31) == 0) red[tid >> 5] = s;
    __syncthreads();
    float sall = red[0];
#pragma unroll
    for (int w = 1; w < 8; ++w) sall += red[w];

    const float inv = 1.0f / sall;
    v0.x *= inv; v0.y *= inv; v0.z *= inv; v0.w *= inv;
    v1.x *= inv; v1.y *= inv; v1.z *= inv; v1.w *= inv;

    p[tid * 2 + 0] = v0;
    p[tid * 2 + 1] = v1;

    __half2 h0 = __floats2half2_rn(v0.x, v0.y);
    __half2 h1 = __floats2half2_rn(v0.z, v0.w);
    __half2 h2 = __floats2half2_rn(v1.x, v1.y);
    __half2 h3 = __floats2half2_rn(v1.z, v1.w);
    uint4 pk = make_uint4(*reinterpret_cast<uint32_t*>(&h0),
                          *reinterpret_cast<uint32_t*>(&h1),
                          *reinterpret_cast<uint32_t*>(&h2),
                          *reinterpret_cast<uint32_t*>(&h3));
    ((uint4*)(Phi + row * (size_t)LV))[tid] = pk;
}

// ---------------------------------------------------------------------------
// Launch: phase-staggered pipeline.
//   stream0: Qsplit; GEMM1 chunk q (4 batches, 1024 CTAs) sequentially.
//   sB:      Vprep chunk q -> evV[q];  after evG1[q]: softmax+GEMM2 chunk q.
// softmax/GEMM2 of chunks 0..2 overlap GEMM1 of chunks 1..3; only chunk 3's
// epilogue (~70us) is exposed. Fixed DAG, kernels+events only.
// ---------------------------------------------------------------------------
extern "C" void kernel_launch(void* const* d_in, const int* in_sizes, int n_in,
                              void* d_out, int out_size)
{
    const float* Q = (const float*)d_in[0];
    const float* V = (const float*)d_in[1];

    float* ctx  = (float*)d_out;                          // [B,Lq,D]
    float* attn = (float*)d_out + (size_t)B_ * LQ * DD;   // [B,Lq,Lv]

    cudaFuncSetAttribute((const void*)mma_f16_gemm<3, 3>,
                         cudaFuncAttributeMaxDynamicSharedMemorySize, GEMM_SMEM);
    cudaFuncSetAttribute((const void*)mma_f16_gemm<1, 6>,
                         cudaFuncAttributeMaxDynamicSharedMemorySize, GEMM_SMEM);

    __half *Qhi, *Qlo, *Vhi, *Vlo, *VThi, *Phi;
    cudaGetSymbolAddress((void**)&Qhi, g_Qhi);
    cudaGetSymbolAddress((void**)&Qlo, g_Qlo);
    cudaGetSymbolAddress((void**)&Vhi, g_Vhi);
    cudaGetSymbolAddress((void**)&Vlo, g_Vlo);
    cudaGetSymbolAddress((void**)&VThi, g_VThi);
    cudaGetSymbolAddress((void**)&Phi, g_Phi);

    static cudaStream_t sB = nullptr;
    static cudaEvent_t evFork = nullptr, evDone = nullptr;
    static cudaEvent_t evV[NCH], evG1[NCH];
    if (!sB) {
        cudaStreamCreateWithFlags(&sB, cudaStreamNonBlocking);
        cudaEventCreateWithFlags(&evFork, cudaEventDisableTiming);
        cudaEventCreateWithFlags(&evDone, cudaEventDisableTiming);
        for (int q = 0; q < NCH; ++q) {
            cudaEventCreateWithFlags(&evV[q], cudaEventDisableTiming);
            cudaEventCreateWithFlags(&evG1[q], cudaEventDisableTiming);
        }
    }

    const size_t QV = (size_t)LQ * DD;    // per-batch Q/V/ctx elements
    const size_t PB = (size_t)LQ * LV;    // per-batch attn elements
    const size_t cQV = (size_t)CB * QV;   // per-chunk elements
    const size_t cPB = (size_t)CB * PB;

    cudaEventRecord(evFork, 0);
    cudaStreamWaitEvent(sB, evFork, 0);

    // ---- sB: V prep per chunk
    for (int q = 0; q < NCH; ++q) {
        dim3 grid(LV / 32, DD / 32, CB);
        v_prep_kernel<<<grid, dim3(32, 8), 0, sB>>>(
            V + q * cQV, Vhi + q * cQV, Vlo + q * cQV, VThi + q * cQV);
        cudaEventRecord(evV[q], sB);
    }

    // ---- stream0: Q split, then GEMM1 per chunk
    split_kernel<<<(int)(NQ / 4 / 256), 256>>>(Q, Qhi, Qlo, (int)(NQ / 4));
    for (int q = 0; q < NCH; ++q) {
        cudaStreamWaitEvent(0, evV[q], 0);
        dim3 grid(LV / 128, LQ / 128, CB);
        mma_f16_gemm<3, 3><<<grid, 256, GEMM_SMEM>>>(
            Qhi + q * cQV, Qlo + q * cQV, Vhi + q * cQV, Vlo + q * cQV,
            attn + q * cPB, LQ, LV, DD);
        cudaEventRecord(evG1[q], 0);
    }

    // ---- sB: softmax + GEMM2 per chunk (overlaps later GEMM1 chunks)
    for (int q = 0; q < NCH; ++q) {
        cudaStreamWaitEvent(sB, evG1[q], 0);
        softmax_kernel<<<CB * LQ, 256, 0, sB>>>(attn + q * cPB, Phi + q * cPB);
        dim3 grid(DD / 128, LQ / 128, CB);
        mma_f16_gemm<1, 6><<<grid, 256, GEMM_SMEM, sB>>>(
            Phi + q * cPB, Phi + q * cPB, VThi + q * cQV, VThi + q * cQV,
            ctx + q * cQV, LQ, DD, LV);
    }
    cudaEventRecord(evDone, sB);
    cudaStreamWaitEvent(0, evDone, 0);
}

// round 14
// speedup vs baseline: 1.5562x; 1.5562x over previous
#include <cuda_runtime.h>
#include <cuda_fp16.h>
#include <cstdint>

// Shape fixed by reference:
//   query [B=16, Lq=2048, D=512] f32, value [B=16, Lv=2048, D=512] f32
//   out = context [B,Lq,D] f32  ||  attn [B,Lq,Lv] f32
static constexpr int B_ = 16, LQ = 2048, LV = 2048, DD = 512;
// asymmetric split: stream A = 6 batches, stream B = 10 batches
static constexpr int BA = 6, BB = B_ - BA;

static constexpr size_t NQ = (size_t)B_ * LQ * DD;
static constexpr size_t NV = (size_t)B_ * LV * DD;
static constexpr size_t NP = (size_t)B_ * LQ * LV;

// fp16 hi/lo scratch (global)
__device__ __half g_Qhi[NQ], g_Qlo[NQ];
__device__ __half g_Vhi[NV], g_Vlo[NV];
__device__ __half g_VThi[NV];                 // [b][d][v]
__device__ __half g_Phi[NP];

// ---------------------------------------------------------------------------
// helpers
// ---------------------------------------------------------------------------
__device__ __forceinline__ void cp16(uint32_t dst, const void* src) {
    asm volatile("cp.async.cg.shared.global [%0], [%1], 16;" :: "r"(dst), "l"(src));
}
#define CP_COMMIT() asm volatile("cp.async.commit_group;" ::: "memory")
template <int N>
__device__ __forceinline__ void cp_wait() {
    asm volatile("cp.async.wait_group %0;" :: "n"(N) : "memory");
}

// split pair (x,y) -> hi half2 (low = x), lo half2
__device__ __forceinline__ void f16_split2(float x, float y,
                                           uint32_t& hp, uint32_t& lp) {
    __half2 h = __floats2half2_rn(x, y);
    hp = *reinterpret_cast<uint32_t*>(&h);
    float2 hf = __half22float2(h);
    __half2 l = __floats2half2_rn(x - hf.x, y - hf.y);
    lp = *reinterpret_cast<uint32_t*>(&l);
}

__device__ __forceinline__ void mma16(float* d, const uint32_t* a, const uint32_t* b) {
    asm volatile(
        "mma.sync.aligned.m16n8k16.row.col.f32.f16.f16.f32 "
        "{%0,%1,%2,%3}, {%4,%5,%6,%7}, {%8,%9}, {%0,%1,%2,%3};"
        : "+f"(d[0]), "+f"(d[1]), "+f"(d[2]), "+f"(d[3])
        : "r"(a[0]), "r"(a[1]), "r"(a[2]), "r"(a[3]), "r"(b[0]), "r"(b[1]));
}

__device__ __forceinline__ void ldm4(uint32_t* r, uint32_t addr) {
    asm volatile("ldmatrix.sync.aligned.m8n8.x4.shared.b16 {%0,%1,%2,%3}, [%4];"
                 : "=r"(r[0]), "=r"(r[1]), "=r"(r[2]), "=r"(r[3]) : "r"(addr));
}

// ---------------------------------------------------------------------------
// fp16 split GEMM:  C[M,N] = A[M,K]*B[N,K]^T, batched via blockIdx.z
// PASSES=3: Ahi*Bhi + Ahi*Blo + Alo*Bhi  (full compensation, 4 tiles/stage)
// PASSES=1: Ahi*Bhi                       (2 tiles/stage, deeper pipeline)
// CTA 128x128, BK=32, 8 warps (2x4 of 64x32), STAGES-deep cp.async,
// XOR-swizzled smem (64B rows, chunk c ^= (r>>1)&3), ldmatrix feeds.
// ---------------------------------------------------------------------------
static constexpr int ROWB   = 64;              // bytes per smem row (32 halves)
static constexpr int TILE_B = 128 * ROWB;      // 8 KB
template <int PASSES> struct StageTiles { static constexpr int v = 4; };
template <> struct StageTiles<1> { static constexpr int v = 2; };
static constexpr int GEMM_SMEM = 96 * 1024;    // both configs use 96 KB

template <int PASSES, int STAGES>
__global__ __launch_bounds__(256, 2)
void mma_f16_gemm(const __half* __restrict__ Ahi,
                  const __half* __restrict__ Alo,
                  const __half* __restrict__ Bhi,
                  const __half* __restrict__ Blo,
                  float* __restrict__ C, int M, int N, int K)
{
    constexpr int STAGE_B = StageTiles<PASSES>::v * TILE_B;
    constexpr int PREF    = STAGES - 1;
    constexpr int BOFF    = (PASSES == 3 ? 2 : 1) * TILE_B;

    extern __shared__ char smc[];
    const uint32_t base = (uint32_t)__cvta_generic_to_shared(smc);

    const int tid = threadIdx.x;
    const int wid = tid >> 5, lane = tid & 31;
    const int gid = lane >> 2, tig = lane & 3;
    const int wm  = wid & 1;
    const int wn  = wid >> 1;

    const size_t bz = blockIdx.z;
    Ahi += bz * (size_t)M * K;  Alo += bz * (size_t)M * K;
    Bhi += bz * (size_t)N * K;  Blo += bz * (size_t)N * K;
    C   += bz * (size_t)M * N;
    const int row0 = blockIdx.y * 128;
    const int col0 = blockIdx.x * 128;

    // loader: chunks of 16B; thread does chunks tid, tid+256
    const int i0 = tid, i1 = tid + 256;
    const int r0 = i0 >> 2, c0 = i0 & 3;
    const int r1 = i1 >> 2, c1 = i1 & 3;
    const uint32_t s0 = (uint32_t)(r0 * ROWB + ((c0 ^ ((r0 >> 1) & 3)) << 4));
    const uint32_t s1 = (uint32_t)(r1 * ROWB + ((c1 ^ ((r1 >> 1) & 3)) << 4));

    auto load_stage = [&](int st, int k0) {
        const uint32_t sb = base + (uint32_t)(st * STAGE_B);
        cp16(sb + s0,            &Ahi[(size_t)(row0 + r0) * K + k0 + c0 * 8]);
        cp16(sb + s1,            &Ahi[(size_t)(row0 + r1) * K + k0 + c1 * 8]);
        if (PASSES == 3) {
            cp16(sb + TILE_B + s0, &Alo[(size_t)(row0 + r0) * K + k0 + c0 * 8]);
            cp16(sb + TILE_B + s1, &Alo[(size_t)(row0 + r1) * K + k0 + c1 * 8]);
        }
        cp16(sb + BOFF + s0,     &Bhi[(size_t)(col0 + r0) * K + k0 + c0 * 8]);
        cp16(sb + BOFF + s1,     &Bhi[(size_t)(col0 + r1) * K + k0 + c1 * 8]);
        if (PASSES == 3) {
            cp16(sb + BOFF + TILE_B + s0, &Blo[(size_t)(col0 + r0) * K + k0 + c0 * 8]);
            cp16(sb + BOFF + TILE_B + s1, &Blo[(size_t)(col0 + r1) * K + k0 + c1 * 8]);
        }
    };

    // ldmatrix lane addressing
    const int a_row16 = ((lane >> 3) & 1) * 8 + (lane & 7);
    const int a_cpar  = (lane >> 4) & 1;
    uint32_t aoff[4]; int aswz[4];
#pragma unroll
    for (int mt = 0; mt < 4; ++mt) {
        const int r = wm * 64 + mt * 16 + a_row16;
        aoff[mt] = (uint32_t)(r * ROWB);
        aswz[mt] = (r >> 1) & 3;
    }
    const int b_nadd = ((lane >> 4) & 1) * 8 + (lane & 7);
    const int b_cpar = (lane >> 3) & 1;
    uint32_t boff[2]; int bswz[2];
#pragma unroll
    for (int p = 0; p < 2; ++p) {
        const int n = wn * 32 + p * 16 + b_nadd;
        boff[p] = (uint32_t)(n * ROWB);
        bswz[p] = (n >> 1) & 3;
    }

    float acc[4][4][4];
#pragma unroll
    for (int mt = 0; mt < 4; ++mt)
#pragma unroll
        for (int nt = 0; nt < 4; ++nt)
#pragma unroll
            for (int i = 0; i < 4; ++i) acc[mt][nt][i] = 0.f;

    const int nsl = K / 32;
#pragma unroll
    for (int s = 0; s < PREF; ++s) {
        load_stage(s, s * 32);
        CP_COMMIT();
    }

    for (int s = 0; s < nsl; ++s) {
        cp_wait<PREF - 1>();   // stage s resident
        __syncthreads();       // all warps done with previous use of this buffer

        if (s + PREF < nsl) {
            load_stage((s + PREF) % STAGES, (s + PREF) * 32);
            CP_COMMIT();
        } else {
            CP_COMMIT();       // empty group keeps count aligned for cp_wait
        }

        const uint32_t stg  = base + (uint32_t)((s % STAGES) * STAGE_B);
        const uint32_t Ahib = stg;
        const uint32_t Bhib = stg + BOFF;

#pragma unroll
        for (int ks = 0; ks < 2; ++ks) {
            uint32_t bhi[4][2], blo[4][2];
#pragma unroll
            for (int p = 0; p < 2; ++p) {
                uint32_t t[4];
                const uint32_t ad = Bhib + boff[p] +
                    (uint32_t)(((ks * 2 + b_cpar) ^ bswz[p]) << 4);
                ldm4(t, ad);
                bhi[2 * p][0] = t[0]; bhi[2 * p][1] = t[1];
                bhi[2 * p + 1][0] = t[2]; bhi[2 * p + 1][1] = t[3];
                if (PASSES == 3) {
                    ldm4(t, ad + TILE_B);
                    blo[2 * p][0] = t[0]; blo[2 * p][1] = t[1];
                    blo[2 * p + 1][0] = t[2]; blo[2 * p + 1][1] = t[3];
                }
            }

#pragma unroll
            for (int mt = 0; mt < 4; ++mt) {
                uint32_t ahi[4], alo[4];
                const uint32_t ad = Ahib + aoff[mt] +
                    (uint32_t)(((ks * 2 + a_cpar) ^ aswz[mt]) << 4);
                ldm4(ahi, ad);
                if (PASSES == 3) ldm4(alo, ad + TILE_B);
#pragma unroll
                for (int nt = 0; nt < 4; ++nt) mma16(acc[mt][nt], ahi, bhi[nt]);
                if (PASSES == 3) {
#pragma unroll
                    for (int nt = 0; nt < 4; ++nt) mma16(acc[mt][nt], ahi, blo[nt]);
#pragma unroll
                    for (int nt = 0; nt < 4; ++nt) mma16(acc[mt][nt], alo, bhi[nt]);
                }
            }
        }
    }

    __syncthreads();
#pragma unroll
    for (int mt = 0; mt < 4; ++mt) {
        const int rb = row0 + wm * 64 + mt * 16 + gid;
#pragma unroll
        for (int nt = 0; nt < 4; ++nt) {
            const int cb = col0 + wn * 32 + nt * 8 + 2 * tig;
            *(float2*)&C[(size_t)rb * N + cb] =
                make_float2(acc[mt][nt][0], acc[mt][nt][1]);
            *(float2*)&C[(size_t)(rb + 8) * N + cb] =
                make_float2(acc[mt][nt][2], acc[mt][nt][3]);
        }
    }
}

// ---------------------------------------------------------------------------
// Q split: fp32 -> fp16 hi/lo
// ---------------------------------------------------------------------------
__global__ __launch_bounds__(256)
void split_kernel(const float* __restrict__ X,
                  __half* __restrict__ hi, __half* __restrict__ lo, int n4)
{
    const int i = blockIdx.x * 256 + threadIdx.x;
    if (i >= n4) return;
    float4 v = ((const float4*)X)[i];
    uint32_t h0, l0, h1, l1;
    f16_split2(v.x, v.y, h0, l0);
    f16_split2(v.z, v.w, h1, l1);
    ((uint2*)hi)[i] = make_uint2(h0, h1);
    ((uint2*)lo)[i] = make_uint2(l0, l1);
}

// ---------------------------------------------------------------------------
// Fused V prep (batched via blockIdx.z): Vhi/Vlo [b][v][d] + VThi [b][d][v]
// ---------------------------------------------------------------------------
__global__ __launch_bounds__(256)
void v_prep_kernel(const float* __restrict__ V,
                   __half* __restrict__ Vhi, __half* __restrict__ Vlo,
                   __half* __restrict__ VThi)
{
    __shared__ float t[32][33];
    const int b = blockIdx.z;
    const float* Vb = V + (size_t)b * LV * DD;
    const size_t ro = (size_t)b * LV * DD;
    const size_t to = (size_t)b * DD * LV;
    const int v0 = blockIdx.x * 32, d0 = blockIdx.y * 32;
    const int tx = threadIdx.x, ty = threadIdx.y;  // 32 x 8
#pragma unroll
    for (int i = 0; i < 32; i += 8) {
        float x = Vb[(size_t)(v0 + ty + i) * DD + d0 + tx];
        t[ty + i][tx] = x;
        __half h = __float2half(x);
        Vhi[ro + (size_t)(v0 + ty + i) * DD + d0 + tx] = h;
        Vlo[ro + (size_t)(v0 + ty + i) * DD + d0 + tx] =
            __float2half(x - __half2float(h));
    }
    __syncthreads();
#pragma unroll
    for (int i = 0; i < 32; i += 8)
        VThi[to + (size_t)(d0 + ty + i) * LV + v0 + tx] =
            __float2half(t[tx][ty + i]);
}

// ---------------------------------------------------------------------------
// In-place row softmax over Lv=2048, emits fp16 hi of P
// ---------------------------------------------------------------------------
__global__ __launch_bounds__(256)
void softmax_kernel(float* __restrict__ attn, __half* __restrict__ Phi)
{
    const size_t row = blockIdx.x;
    float4* p = (float4*)(attn + row * (size_t)LV);
    const int tid = threadIdx.x;

    float4 v0 = p[tid * 2 + 0];
    float4 v1 = p[tid * 2 + 1];

    float m = fmaxf(fmaxf(fmaxf(v0.x, v0.y), fmaxf(v0.z, v0.w)),
                    fmaxf(fmaxf(v1.x, v1.y), fmaxf(v1.z, v1.w)));
#pragma unroll
    for (int o = 16; o > 0; o >>= 1)
        m = fmaxf(m, __shfl_xor_sync(0xffffffffu, m, o));

    __shared__ float red[8];
    if ((tid & 31) == 0) red[tid >> 5] = m;
    __syncthreads();
    float mall = red[0];
#pragma unroll
    for (int w = 1; w < 8; ++w) mall = fmaxf(mall, red[w]);
    __syncthreads();

    v0.x = __expf(v0.x - mall); v0.y = __expf(v0.y - mall);
    v0.z = __expf(v0.z - mall); v0.w = __expf(v0.w - mall);
    v1.x = __expf(v1.x - mall); v1.y = __expf(v1.y - mall);
    v1.z = __expf(v1.z - mall); v1.w = __expf(v1.w - mall);

    float s = v0.x + v0.y + v0.z + v0.w + v1.x + v1.y + v1.z + v1.w;
#pragma unroll
    for (int o = 16; o > 0; o >>= 1)
        s += __shfl_xor_sync(0xffffffffu, s, o);
    if ((tid & 31) == 0) red[tid >> 5] = s;
    __syncthreads();
    float sall = red[0];
#pragma unroll
    for (int w = 1; w < 8; ++w) sall += red[w];

    const float inv = 1.0f / sall;
    v0.x *= inv; v0.y *= inv; v0.z *= inv; v0.w *= inv;
    v1.x *= inv; v1.y *= inv; v1.z *= inv; v1.w *= inv;

    p[tid * 2 + 0] = v0;
    p[tid * 2 + 1] = v1;

    __half2 h0 = __floats2half2_rn(v0.x, v0.y);
    __half2 h1 = __floats2half2_rn(v0.z, v0.w);
    __half2 h2 = __floats2half2_rn(v1.x, v1.y);
    __half2 h3 = __floats2half2_rn(v1.z, v1.w);
    uint4 pk = make_uint4(*reinterpret_cast<uint32_t*>(&h0),
                          *reinterpret_cast<uint32_t*>(&h1),
                          *reinterpret_cast<uint32_t*>(&h2),
                          *reinterpret_cast<uint32_t*>(&h3));
    ((uint4*)(Phi + row * (size_t)LV))[tid] = pk;
}

// ---------------------------------------------------------------------------
// Launch: two INDEPENDENT streams (no cross-stream events except fork/join),
// asymmetric 6/10 batch split. Stream A finishes GEMM1 early and its
// softmax/GEMM2 overlap stream B's remaining GEMM1 work-conservingly.
// ---------------------------------------------------------------------------
extern "C" void kernel_launch(void* const* d_in, const int* in_sizes, int n_in,
                              void* d_out, int out_size)
{
    const float* Q = (const float*)d_in[0];
    const float* V = (const float*)d_in[1];

    float* ctx  = (float*)d_out;                          // [B,Lq,D]
    float* attn = (float*)d_out + (size_t)B_ * LQ * DD;   // [B,Lq,Lv]

    cudaFuncSetAttribute((const void*)mma_f16_gemm<3, 3>,
                         cudaFuncAttributeMaxDynamicSharedMemorySize, GEMM_SMEM);
    cudaFuncSetAttribute((const void*)mma_f16_gemm<1, 6>,
                         cudaFuncAttributeMaxDynamicSharedMemorySize, GEMM_SMEM);

    __half *Qhi, *Qlo, *Vhi, *Vlo, *VThi, *Phi;
    cudaGetSymbolAddress((void**)&Qhi, g_Qhi);
    cudaGetSymbolAddress((void**)&Qlo, g_Qlo);
    cudaGetSymbolAddress((void**)&Vhi, g_Vhi);
    cudaGetSymbolAddress((void**)&Vlo, g_Vlo);
    cudaGetSymbolAddress((void**)&VThi, g_VThi);
    cudaGetSymbolAddress((void**)&Phi, g_Phi);

    static cudaStream_t sB = nullptr;
    static cudaEvent_t evFork = nullptr, evDone = nullptr;
    if (!sB) {
        cudaStreamCreateWithFlags(&sB, cudaStreamNonBlocking);
        cudaEventCreateWithFlags(&evFork, cudaEventDisableTiming);
        cudaEventCreateWithFlags(&evDone, cudaEventDisableTiming);
    }

    const size_t QV = (size_t)LQ * DD;    // per-batch Q/V/ctx elements
    const size_t PB = (size_t)LQ * LV;    // per-batch attn elements

    cudaEventRecord(evFork, 0);
    cudaStreamWaitEvent(sB, evFork, 0);

    const int   nb[2]  = {BA, BB};        // batches per stream
    const int   ob[2]  = {0, BA};         // batch offsets

    for (int h = 0; h < 2; ++h) {
        cudaStream_t st = (h == 0) ? (cudaStream_t)0 : sB;
        const int    cb = nb[h];
        const size_t qo = (size_t)ob[h] * QV;
        const size_t po = (size_t)ob[h] * PB;
        const size_t qn = (size_t)cb * QV;

        split_kernel<<<(int)(qn / 4 / 256), 256, 0, st>>>(
            Q + qo, Qhi + qo, Qlo + qo, (int)(qn / 4));
        {
            dim3 grid(LV / 32, DD / 32, cb);
            v_prep_kernel<<<grid, dim3(32, 8), 0, st>>>(
                V + qo, Vhi + qo, Vlo + qo, VThi + qo);
        }
        {
            dim3 grid(LV / 128, LQ / 128, cb);
            mma_f16_gemm<3, 3><<<grid, 256, GEMM_SMEM, st>>>(
                Qhi + qo, Qlo + qo, Vhi + qo, Vlo + qo, attn + po, LQ, LV, DD);
        }
        softmax_kernel<<<cb * LQ, 256, 0, st>>>(attn + po, Phi + po);
        {
            dim3 grid(DD / 128, LQ / 128, cb);
            mma_f16_gemm<1, 6><<<grid, 256, GEMM_SMEM, st>>>(
                Phi + po, Phi + po, VThi + qo, VThi + qo, ctx + qo, LQ, DD, LV);
        }
    }

    cudaEventRecord(evDone, sB);
    cudaStreamWaitEvent(0, evDone, 0);
}

// round 15
// speedup vs baseline: 1.5897x; 1.0215x over previous
#include <cuda_runtime.h>
#include <cuda_fp16.h>
#include <cstdint>

// Shape fixed by reference:
//   query [B=16, Lq=2048, D=512] f32, value [B=16, Lv=2048, D=512] f32
//   out = context [B,Lq,D] f32  ||  attn [B,Lq,Lv] f32
static constexpr int B_ = 16, LQ = 2048, LV = 2048, DD = 512;
static constexpr int HB = B_ / 2;             // batches per stream

static constexpr size_t NQ = (size_t)B_ * LQ * DD;
static constexpr size_t NV = (size_t)B_ * LV * DD;
static constexpr size_t NP = (size_t)B_ * LQ * LV;

// fp16 hi/lo scratch (global)
__device__ __half g_Qhi[NQ], g_Qlo[NQ];
__device__ __half g_Vhi[NV], g_Vlo[NV];
__device__ __half g_VThi[NV];                 // [b][d][v]
__device__ __half g_Phi[NP];

// ---------------------------------------------------------------------------
// helpers
// ---------------------------------------------------------------------------
__device__ __forceinline__ void cp16(uint32_t dst, const void* src) {
    asm volatile("cp.async.cg.shared.global [%0], [%1], 16;" :: "r"(dst), "l"(src));
}
#define CP_COMMIT() asm volatile("cp.async.commit_group;" ::: "memory")
template <int N>
__device__ __forceinline__ void cp_wait() {
    asm volatile("cp.async.wait_group %0;" :: "n"(N) : "memory");
}

// split pair (x,y) -> hi half2 (low = x), lo half2
__device__ __forceinline__ void f16_split2(float x, float y,
                                           uint32_t& hp, uint32_t& lp) {
    __half2 h = __floats2half2_rn(x, y);
    hp = *reinterpret_cast<uint32_t*>(&h);
    float2 hf = __half22float2(h);
    __half2 l = __floats2half2_rn(x - hf.x, y - hf.y);
    lp = *reinterpret_cast<uint32_t*>(&l);
}

__device__ __forceinline__ void mma16(float* d, const uint32_t* a, const uint32_t* b) {
    asm volatile(
        "mma.sync.aligned.m16n8k16.row.col.f32.f16.f16.f32 "
        "{%0,%1,%2,%3}, {%4,%5,%6,%7}, {%8,%9}, {%0,%1,%2,%3};"
        : "+f"(d[0]), "+f"(d[1]), "+f"(d[2]), "+f"(d[3])
        : "r"(a[0]), "r"(a[1]), "r"(a[2]), "r"(a[3]), "r"(b[0]), "r"(b[1]));
}

__device__ __forceinline__ void ldm4(uint32_t* r, uint32_t addr) {
    asm volatile("ldmatrix.sync.aligned.m8n8.x4.shared.b16 {%0,%1,%2,%3}, [%4];"
                 : "=r"(r[0]), "=r"(r[1]), "=r"(r[2]), "=r"(r[3]) : "r"(addr));
}

// ===========================================================================
// GEMM1: fp16 split, PASSES=3 (Ahi*Bhi + Ahi*Blo + Alo*Bhi), BK=32.
// CTA 128x128, 8 warps (2x4 of 64x32), 3-stage cp.async, 64B rows with
// XOR swizzle (chunk c ^= (r>>1)&3), ldmatrix feeds. (Unchanged from R9.)
// ===========================================================================
static constexpr int ROWB   = 64;              // bytes per smem row (32 halves)
static constexpr int TILE_B = 128 * ROWB;      // 8 KB
static constexpr int G1_STAGE_B = 4 * TILE_B;  // 32 KB
static constexpr int GEMM_SMEM = 96 * 1024;

__global__ __launch_bounds__(256, 2)
void mma_f16_gemm3(const __half* __restrict__ Ahi,
                   const __half* __restrict__ Alo,
                   const __half* __restrict__ Bhi,
                   const __half* __restrict__ Blo,
                   float* __restrict__ C, int M, int N, int K)
{
    constexpr int STAGES = 3, PREF = 2;

    extern __shared__ char smc[];
    const uint32_t base = (uint32_t)__cvta_generic_to_shared(smc);

    const int tid = threadIdx.x;
    const int wid = tid >> 5, lane = tid & 31;
    const int gid = lane >> 2, tig = lane & 3;
    const int wm  = wid & 1;
    const int wn  = wid >> 1;

    const size_t bz = blockIdx.z;
    Ahi += bz * (size_t)M * K;  Alo += bz * (size_t)M * K;
    Bhi += bz * (size_t)N * K;  Blo += bz * (size_t)N * K;
    C   += bz * (size_t)M * N;
    const int row0 = blockIdx.y * 128;
    const int col0 = blockIdx.x * 128;

    const int i0 = tid, i1 = tid + 256;
    const int r0 = i0 >> 2, c0 = i0 & 3;
    const int r1 = i1 >> 2, c1 = i1 & 3;
    const uint32_t s0 = (uint32_t)(r0 * ROWB + ((c0 ^ ((r0 >> 1) & 3)) << 4));
    const uint32_t s1 = (uint32_t)(r1 * ROWB + ((c1 ^ ((r1 >> 1) & 3)) << 4));

    auto load_stage = [&](int st, int k0) {
        const uint32_t sb = base + (uint32_t)(st * G1_STAGE_B);
        cp16(sb + s0,                  &Ahi[(size_t)(row0 + r0) * K + k0 + c0 * 8]);
        cp16(sb + s1,                  &Ahi[(size_t)(row0 + r1) * K + k0 + c1 * 8]);
        cp16(sb + TILE_B + s0,         &Alo[(size_t)(row0 + r0) * K + k0 + c0 * 8]);
        cp16(sb + TILE_B + s1,         &Alo[(size_t)(row0 + r1) * K + k0 + c1 * 8]);
        cp16(sb + 2 * TILE_B + s0,     &Bhi[(size_t)(col0 + r0) * K + k0 + c0 * 8]);
        cp16(sb + 2 * TILE_B + s1,     &Bhi[(size_t)(col0 + r1) * K + k0 + c1 * 8]);
        cp16(sb + 3 * TILE_B + s0,     &Blo[(size_t)(col0 + r0) * K + k0 + c0 * 8]);
        cp16(sb + 3 * TILE_B + s1,     &Blo[(size_t)(col0 + r1) * K + k0 + c1 * 8]);
    };

    const int a_row16 = ((lane >> 3) & 1) * 8 + (lane & 7);
    const int a_cpar  = (lane >> 4) & 1;
    uint32_t aoff[4]; int aswz[4];
#pragma unroll
    for (int mt = 0; mt < 4; ++mt) {
        const int r = wm * 64 + mt * 16 + a_row16;
        aoff[mt] = (uint32_t)(r * ROWB);
        aswz[mt] = (r >> 1) & 3;
    }
    const int b_nadd = ((lane >> 4) & 1) * 8 + (lane & 7);
    const int b_cpar = (lane >> 3) & 1;
    uint32_t boff[2]; int bswz[2];
#pragma unroll
    for (int p = 0; p < 2; ++p) {
        const int n = wn * 32 + p * 16 + b_nadd;
        boff[p] = (uint32_t)(n * ROWB);
        bswz[p] = (n >> 1) & 3;
    }

    float acc[4][4][4];
#pragma unroll
    for (int mt = 0; mt < 4; ++mt)
#pragma unroll
        for (int nt = 0; nt < 4; ++nt)
#pragma unroll
            for (int i = 0; i < 4; ++i) acc[mt][nt][i] = 0.f;

    const int nsl = K / 32;
#pragma unroll
    for (int s = 0; s < PREF; ++s) { load_stage(s, s * 32); CP_COMMIT(); }

    for (int s = 0; s < nsl; ++s) {
        cp_wait<PREF - 1>();
        __syncthreads();

        if (s + PREF < nsl) {
            load_stage((s + PREF) % STAGES, (s + PREF) * 32);
            CP_COMMIT();
        } else {
            CP_COMMIT();
        }

        const uint32_t stg  = base + (uint32_t)((s % STAGES) * G1_STAGE_B);
        const uint32_t Ahib = stg;
        const uint32_t Bhib = stg + 2 * TILE_B;

#pragma unroll
        for (int ks = 0; ks < 2; ++ks) {
            uint32_t bhi[4][2], blo[4][2];
#pragma unroll
            for (int p = 0; p < 2; ++p) {
                uint32_t t[4];
                const uint32_t ad = Bhib + boff[p] +
                    (uint32_t)(((ks * 2 + b_cpar) ^ bswz[p]) << 4);
                ldm4(t, ad);
                bhi[2 * p][0] = t[0]; bhi[2 * p][1] = t[1];
                bhi[2 * p + 1][0] = t[2]; bhi[2 * p + 1][1] = t[3];
                ldm4(t, ad + TILE_B);
                blo[2 * p][0] = t[0]; blo[2 * p][1] = t[1];
                blo[2 * p + 1][0] = t[2]; blo[2 * p + 1][1] = t[3];
            }

#pragma unroll
            for (int mt = 0; mt < 4; ++mt) {
                uint32_t ahi[4], alo[4];
                const uint32_t ad = Ahib + aoff[mt] +
                    (uint32_t)(((ks * 2 + a_cpar) ^ aswz[mt]) << 4);
                ldm4(ahi, ad);
                ldm4(alo, ad + TILE_B);
#pragma unroll
                for (int nt = 0; nt < 4; ++nt) mma16(acc[mt][nt], ahi, bhi[nt]);
#pragma unroll
                for (int nt = 0; nt < 4; ++nt) mma16(acc[mt][nt], ahi, blo[nt]);
#pragma unroll
                for (int nt = 0; nt < 4; ++nt) mma16(acc[mt][nt], alo, bhi[nt]);
            }
        }
    }

    __syncthreads();
#pragma unroll
    for (int mt = 0; mt < 4; ++mt) {
        const int rb = row0 + wm * 64 + mt * 16 + gid;
#pragma unroll
        for (int nt = 0; nt < 4; ++nt) {
            const int cb = col0 + wn * 32 + nt * 8 + 2 * tig;
            *(float2*)&C[(size_t)rb * N + cb] =
                make_float2(acc[mt][nt][0], acc[mt][nt][1]);
            *(float2*)&C[(size_t)(rb + 8) * N + cb] =
                make_float2(acc[mt][nt][2], acc[mt][nt][3]);
        }
    }
}

// ===========================================================================
// GEMM2: single-product fp16 GEMM (Phi * VThi^T), BK=64 with 128B rows and
// SW128 swizzle (chunk c ^= r&7). 3-stage x 32KB pipeline, half the barriers
// per K vs BK=32. CTA 128x128, same 2x4 warp layout.
// ===========================================================================
static constexpr int ROWB2   = 128;            // bytes per smem row (64 halves)
static constexpr int TILE_B2 = 128 * ROWB2;    // 16 KB
static constexpr int G2_STAGE_B = 2 * TILE_B2; // A + B = 32 KB

__global__ __launch_bounds__(256, 2)
void mma_f16_gemm1(const __half* __restrict__ A,
                   const __half* __restrict__ Bm,
                   float* __restrict__ C, int M, int N, int K)
{
    constexpr int STAGES = 3, PREF = 2;

    extern __shared__ char smc[];
    const uint32_t base = (uint32_t)__cvta_generic_to_shared(smc);

    const int tid = threadIdx.x;
    const int wid = tid >> 5, lane = tid & 31;
    const int gid = lane >> 2, tig = lane & 3;
    const int wm  = wid & 1;
    const int wn  = wid >> 1;

    const size_t bz = blockIdx.z;
    A  += bz * (size_t)M * K;
    Bm += bz * (size_t)N * K;
    C  += bz * (size_t)M * N;
    const int row0 = blockIdx.y * 128;
    const int col0 = blockIdx.x * 128;

    // loader: tile = 128 rows x 8 chunks(16B) = 1024 chunks; 4 per thread
    uint32_t ls[4]; int lr[4], lc[4];
#pragma unroll
    for (int k = 0; k < 4; ++k) {
        const int i = tid + 256 * k;
        lr[k] = i >> 3; lc[k] = i & 7;
        ls[k] = (uint32_t)(lr[k] * ROWB2 + ((lc[k] ^ (lr[k] & 7)) << 4));
    }

    auto load_stage = [&](int st, int k0) {
        const uint32_t sb = base + (uint32_t)(st * G2_STAGE_B);
#pragma unroll
        for (int k = 0; k < 4; ++k) {
            cp16(sb + ls[k],           &A[(size_t)(row0 + lr[k]) * K + k0 + lc[k] * 8]);
            cp16(sb + TILE_B2 + ls[k], &Bm[(size_t)(col0 + lr[k]) * K + k0 + lc[k] * 8]);
        }
    };

    // ldmatrix lane addressing (128B rows, swizzle r&7)
    const int a_row16 = ((lane >> 3) & 1) * 8 + (lane & 7);
    const int a_cpar  = (lane >> 4) & 1;
    uint32_t aoff[4]; int aswz[4];
#pragma unroll
    for (int mt = 0; mt < 4; ++mt) {
        const int r = wm * 64 + mt * 16 + a_row16;
        aoff[mt] = (uint32_t)(r * ROWB2);
        aswz[mt] = r & 7;
    }
    const int b_nadd = ((lane >> 4) & 1) * 8 + (lane & 7);
    const int b_cpar = (lane >> 3) & 1;
    uint32_t boff[2]; int bswz[2];
#pragma unroll
    for (int p = 0; p < 2; ++p) {
        const int n = wn * 32 + p * 16 + b_nadd;
        boff[p] = (uint32_t)(n * ROWB2);
        bswz[p] = n & 7;
    }

    float acc[4][4][4];
#pragma unroll
    for (int mt = 0; mt < 4; ++mt)
#pragma unroll
        for (int nt = 0; nt < 4; ++nt)
#pragma unroll
            for (int i = 0; i < 4; ++i) acc[mt][nt][i] = 0.f;

    const int nsl = K / 64;
#pragma unroll
    for (int s = 0; s < PREF; ++s) { load_stage(s, s * 64); CP_COMMIT(); }

    for (int s = 0; s < nsl; ++s) {
        cp_wait<PREF - 1>();
        __syncthreads();

        if (s + PREF < nsl) {
            load_stage((s + PREF) % STAGES, (s + PREF) * 64);
            CP_COMMIT();
        } else {
            CP_COMMIT();
        }

        const uint32_t stg = base + (uint32_t)((s % STAGES) * G2_STAGE_B);

#pragma unroll
        for (int ks = 0; ks < 4; ++ks) {          // four k16 steps per BK=64
            uint32_t bhi[4][2];
#pragma unroll
            for (int p = 0; p < 2; ++p) {
                uint32_t t[4];
                const uint32_t ad = stg + TILE_B2 + boff[p] +
                    (uint32_t)(((ks * 2 + b_cpar) ^ bswz[p]) << 4);
                ldm4(t, ad);
                bhi[2 * p][0] = t[0]; bhi[2 * p][1] = t[1];
                bhi[2 * p + 1][0] = t[2]; bhi[2 * p + 1][1] = t[3];
            }
#pragma unroll
            for (int mt = 0; mt < 4; ++mt) {
                uint32_t ahi[4];
                const uint32_t ad = stg + aoff[mt] +
                    (uint32_t)(((ks * 2 + a_cpar) ^ aswz[mt]) << 4);
                ldm4(ahi, ad);
#pragma unroll
                for (int nt = 0; nt < 4; ++nt) mma16(acc[mt][nt], ahi, bhi[nt]);
            }
        }
    }

    __syncthreads();
#pragma unroll
    for (int mt = 0; mt < 4; ++mt) {
        const int rb = row0 + wm * 64 + mt * 16 + gid;
#pragma unroll
        for (int nt = 0; nt < 4; ++nt) {
            const int cb = col0 + wn * 32 + nt * 8 + 2 * tig;
            *(float2*)&C[(size_t)rb * N + cb] =
                make_float2(acc[mt][nt][0], acc[mt][nt][1]);
            *(float2*)&C[(size_t)(rb + 8) * N + cb] =
                make_float2(acc[mt][nt][2], acc[mt][nt][3]);
        }
    }
}

// ---------------------------------------------------------------------------
// Q split: fp32 -> fp16 hi/lo
// ---------------------------------------------------------------------------
__global__ __launch_bounds__(256)
void split_kernel(const float* __restrict__ X,
                  __half* __restrict__ hi, __half* __restrict__ lo, int n4)
{
    const int i = blockIdx.x * 256 + threadIdx.x;
    if (i >= n4) return;
    float4 v = ((const float4*)X)[i];
    uint32_t h0, l0, h1, l1;
    f16_split2(v.x, v.y, h0, l0);
    f16_split2(v.z, v.w, h1, l1);
    ((uint2*)hi)[i] = make_uint2(h0, h1);
    ((uint2*)lo)[i] = make_uint2(l0, l1);
}

// ---------------------------------------------------------------------------
// Fused V prep (batched via blockIdx.z): Vhi/Vlo [b][v][d] + VThi [b][d][v]
// ---------------------------------------------------------------------------
__global__ __launch_bounds__(256)
void v_prep_kernel(const float* __restrict__ V,
                   __half* __restrict__ Vhi, __half* __restrict__ Vlo,
                   __half* __restrict__ VThi)
{
    __shared__ float t[32][33];
    const int b = blockIdx.z;
    const float* Vb = V + (size_t)b * LV * DD;
    const size_t ro = (size_t)b * LV * DD;
    const size_t to = (size_t)b * DD * LV;
    const int v0 = blockIdx.x * 32, d0 = blockIdx.y * 32;
    const int tx = threadIdx.x, ty = threadIdx.y;  // 32 x 8
#pragma unroll
    for (int i = 0; i < 32; i += 8) {
        float x = Vb[(size_t)(v0 + ty + i) * DD + d0 + tx];
        t[ty + i][tx] = x;
        __half h = __float2half(x);
        Vhi[ro + (size_t)(v0 + ty + i) * DD + d0 + tx] = h;
        Vlo[ro + (size_t)(v0 + ty + i) * DD + d0 + tx] =
            __float2half(x - __half2float(h));
    }
    __syncthreads();
#pragma unroll
    for (int i = 0; i < 32; i += 8)
        VThi[to + (size_t)(d0 + ty + i) * LV + v0 + tx] =
            __float2half(t[tx][ty + i]);
}

// ---------------------------------------------------------------------------
// In-place row softmax over Lv=2048, emits fp16 hi of P
// ---------------------------------------------------------------------------
__global__ __launch_bounds__(256)
void softmax_kernel(float* __restrict__ attn, __half* __restrict__ Phi)
{
    const size_t row = blockIdx.x;
    float4* p = (float4*)(attn + row * (size_t)LV);
    const int tid = threadIdx.x;

    float4 v0 = p[tid * 2 + 0];
    float4 v1 = p[tid * 2 + 1];

    float m = fmaxf(fmaxf(fmaxf(v0.x, v0.y), fmaxf(v0.z, v0.w)),
                    fmaxf(fmaxf(v1.x, v1.y), fmaxf(v1.z, v1.w)));
#pragma unroll
    for (int o = 16; o > 0; o >>= 1)
        m = fmaxf(m, __shfl_xor_sync(0xffffffffu, m, o));

    __shared__ float red[8];
    if ((tid & 31) == 0) red[tid >> 5] = m;
    __syncthreads();
    float mall = red[0];
#pragma unroll
    for (int w = 1; w < 8; ++w) mall = fmaxf(mall, red[w]);
    __syncthreads();

    v0.x = __expf(v0.x - mall); v0.y = __expf(v0.y - mall);
    v0.z = __expf(v0.z - mall); v0.w = __expf(v0.w - mall);
    v1.x = __expf(v1.x - mall); v1.y = __expf(v1.y - mall);
    v1.z = __expf(v1.z - mall); v1.w = __expf(v1.w - mall);

    float s = v0.x + v0.y + v0.z + v0.w + v1.x + v1.y + v1.z + v1.w;
#pragma unroll
    for (int o = 16; o > 0; o >>= 1)
        s += __shfl_xor_sync(0xffffffffu, s, o);
    if ((tid & 31) == 0) red[tid >> 5] = s;
    __syncthreads();
    float sall = red[0];
#pragma unroll
    for (int w = 1; w < 8; ++w) sall += red[w];

    const float inv = 1.0f / sall;
    v0.x *= inv; v0.y *= inv; v0.z *= inv; v0.w *= inv;
    v1.x *= inv; v1.y *= inv; v1.z *= inv; v1.w *= inv;

    p[tid * 2 + 0] = v0;
    p[tid * 2 + 1] = v1;

    __half2 h0 = __floats2half2_rn(v0.x, v0.y);
    __half2 h1 = __floats2half2_rn(v0.z, v0.w);
    __half2 h2 = __floats2half2_rn(v1.x, v1.y);
    __half2 h3 = __floats2half2_rn(v1.z, v1.w);
    uint4 pk = make_uint4(*reinterpret_cast<uint32_t*>(&h0),
                          *reinterpret_cast<uint32_t*>(&h1),
                          *reinterpret_cast<uint32_t*>(&h2),
                          *reinterpret_cast<uint32_t*>(&h3));
    ((uint4*)(Phi + row * (size_t)LV))[tid] = pk;
}

// ---------------------------------------------------------------------------
// Launch: two independent streams (fork/join only), 8/8 batch split (best
// measured structure), GEMM2 upgraded to BK=64.
// ---------------------------------------------------------------------------
extern "C" void kernel_launch(void* const* d_in, const int* in_sizes, int n_in,
                              void* d_out, int out_size)
{
    const float* Q = (const float*)d_in[0];
    const float* V = (const float*)d_in[1];

    float* ctx  = (float*)d_out;                          // [B,Lq,D]
    float* attn = (float*)d_out + (size_t)B_ * LQ * DD;   // [B,Lq,Lv]

    cudaFuncSetAttribute((const void*)mma_f16_gemm3,
                         cudaFuncAttributeMaxDynamicSharedMemorySize, GEMM_SMEM);
    cudaFuncSetAttribute((const void*)mma_f16_gemm1,
                         cudaFuncAttributeMaxDynamicSharedMemorySize, GEMM_SMEM);

    __half *Qhi, *Qlo, *Vhi, *Vlo, *VThi, *Phi;
    cudaGetSymbolAddress((void**)&Qhi, g_Qhi);
    cudaGetSymbolAddress((void**)&Qlo, g_Qlo);
    cudaGetSymbolAddress((void**)&Vhi, g_Vhi);
    cudaGetSymbolAddress((void**)&Vlo, g_Vlo);
    cudaGetSymbolAddress((void**)&VThi, g_VThi);
    cudaGetSymbolAddress((void**)&Phi, g_Phi);

    static cudaStream_t sB = nullptr;
    static cudaEvent_t evFork = nullptr, evDone = nullptr;
    if (!sB) {
        cudaStreamCreateWithFlags(&sB, cudaStreamNonBlocking);
        cudaEventCreateWithFlags(&evFork, cudaEventDisableTiming);
        cudaEventCreateWithFlags(&evDone, cudaEventDisableTiming);
    }

    const size_t QV = (size_t)LQ * DD;    // per-batch Q/V/ctx elements
    const size_t PB = (size_t)LQ * LV;    // per-batch attn elements
    const size_t hQV = (size_t)HB * QV;
    const size_t hPB = (size_t)HB * PB;

    cudaEventRecord(evFork, 0);
    cudaStreamWaitEvent(sB, evFork, 0);

    for (int h = 0; h < 2; ++h) {
        cudaStream_t st = (h == 0) ? (cudaStream_t)0 : sB;
        const size_t qo = h * hQV, po = h * hPB;

        split_kernel<<<(int)(hQV / 4 / 256), 256, 0, st>>>(
            Q + qo, Qhi + qo, Qlo + qo, (int)(hQV / 4));
        {
            dim3 grid(LV / 32, DD / 32, HB);
            v_prep_kernel<<<grid, dim3(32, 8), 0, st>>>(
                V + qo, Vhi + qo, Vlo + qo, VThi + qo);
        }
        {
            dim3 grid(LV / 128, LQ / 128, HB);
            mma_f16_gemm3<<<grid, 256, GEMM_SMEM, st>>>(
                Qhi + qo, Qlo + qo, Vhi + qo, Vlo + qo, attn + po, LQ, LV, DD);
        }
        softmax_kernel<<<HB * LQ, 256, 0, st>>>(attn + po, Phi + po);
        {
            dim3 grid(DD / 128, LQ / 128, HB);
            mma_f16_gemm1<<<grid, 256, GEMM_SMEM, st>>>(
                Phi + po, VThi + qo, ctx + qo, LQ, DD, LV);
        }
    }

    cudaEventRecord(evDone, sB);
    cudaStreamWaitEvent(0, evDone, 0);
}